// round 3
// baseline (speedup 1.0000x reference)
#include <cuda_runtime.h>

#define N_NODES 50000
#define N_EDGES 800000
#define ET (N_EDGES + N_NODES)   // with self loops
#define FDIM 128
#define HEADS 4
#define HID 32
#define N_GRAPHS 64
#define OUT_CH 10
#define NEG 0.2f

// ---------------- scratch (static device globals; allocation-free) ----------------
__device__ float g_h[(size_t)N_NODES * FDIM];     // GEMM output (pre-activation h)
__device__ float g_buf[(size_t)N_NODES * FDIM];   // layer output (post relu+bias)
__device__ float g_asrc[N_NODES * HEADS];
__device__ float g_adst[N_NODES * HEADS];
__device__ int   g_counts[N_NODES];
__device__ int   g_off[N_NODES + 1];
__device__ int   g_cur[N_NODES];
__device__ int   g_csrc[ET];

__device__ __forceinline__ float lrelu(float x) { return x > 0.f ? x : NEG * x; }

// ---------------- CSR build ----------------
__global__ void k_zero_counts() {
    int i = blockIdx.x * blockDim.x + threadIdx.x;
    if (i < N_NODES) g_counts[i] = 0;
}

__global__ void k_hist(const int* __restrict__ ei) {
    int i = blockIdx.x * blockDim.x + threadIdx.x;
    if (i >= ET) return;
    int d = (i < N_EDGES) ? ei[N_EDGES + i] : (i - N_EDGES);
    atomicAdd(&g_counts[d], 1);
}

__global__ void k_scan() {   // single block, 1024 threads
    __shared__ int part[1024];
    int tid = threadIdx.x;
    const int PER = (N_NODES + 1023) / 1024;   // 49
    int base = tid * PER;
    int s = 0;
    for (int i = 0; i < PER; i++) {
        int idx = base + i;
        if (idx < N_NODES) s += g_counts[idx];
    }
    part[tid] = s;
    __syncthreads();
    for (int off = 1; off < 1024; off <<= 1) {
        int v = (tid >= off) ? part[tid - off] : 0;
        __syncthreads();
        part[tid] += v;
        __syncthreads();
    }
    int run = (tid > 0) ? part[tid - 1] : 0;
    for (int i = 0; i < PER; i++) {
        int idx = base + i;
        if (idx < N_NODES) {
            g_off[idx] = run;
            g_cur[idx] = run;
            run += g_counts[idx];
        }
    }
    if (tid == 1023) g_off[N_NODES] = part[1023];
}

__global__ void k_scatter(const int* __restrict__ ei) {
    int i = blockIdx.x * blockDim.x + threadIdx.x;
    if (i >= ET) return;
    int s, d;
    if (i < N_EDGES) { s = ei[i]; d = ei[N_EDGES + i]; }
    else             { s = i - N_EDGES; d = s; }
    int pos = atomicAdd(&g_cur[d], 1);
    g_csrc[pos] = s;
}

// ---------------- dense GEMM: g_h[N,128] = X[N,128] @ W[128,128] ----------------
// X = Xext if non-null, else g_buf (previous layer output).
// 64-row x 128-col tile per 256-thread block; 4x8 microtile per thread; K tiled by 32.
__global__ void __launch_bounds__(256) k_gemm(const float* __restrict__ Xext,
                                              const float* __restrict__ W) {
    const float* X = Xext ? Xext : (const float*)g_buf;
    __shared__ float xs[64][33];
    __shared__ float ws[32][128];
    int tid  = threadIdx.x;
    int row0 = blockIdx.x * 64;
    int tr = (tid >> 4) << 2;     // 0..60
    int tc = (tid & 15) << 3;     // 0..120
    float acc[4][8];
#pragma unroll
    for (int r = 0; r < 4; r++)
#pragma unroll
        for (int c = 0; c < 8; c++) acc[r][c] = 0.f;

    for (int kt = 0; kt < 128; kt += 32) {
        for (int i = tid; i < 64 * 32; i += 256) {
            int r = i >> 5, k = i & 31;
            int gr = row0 + r;
            xs[r][k] = (gr < N_NODES) ? X[(size_t)gr * FDIM + kt + k] : 0.f;
        }
        for (int i = tid; i < 32 * 128; i += 256) {
            int k = i >> 7, c = i & 127;
            ws[k][c] = W[(kt + k) * FDIM + c];
        }
        __syncthreads();
#pragma unroll
        for (int k = 0; k < 32; k++) {
            float xv[4], wv[8];
#pragma unroll
            for (int r = 0; r < 4; r++) xv[r] = xs[tr + r][k];
#pragma unroll
            for (int c = 0; c < 8; c++) wv[c] = ws[k][tc + c];
#pragma unroll
            for (int r = 0; r < 4; r++)
#pragma unroll
                for (int c = 0; c < 8; c++) acc[r][c] = fmaf(xv[r], wv[c], acc[r][c]);
        }
        __syncthreads();
    }
#pragma unroll
    for (int r = 0; r < 4; r++) {
        int gr = row0 + tr + r;
        if (gr < N_NODES) {
            float4* dst = (float4*)&g_h[(size_t)gr * FDIM + tc];
            dst[0] = make_float4(acc[r][0], acc[r][1], acc[r][2], acc[r][3]);
            dst[1] = make_float4(acc[r][4], acc[r][5], acc[r][6], acc[r][7]);
        }
    }
}

// ---------------- per-node attention dot products (reads g_h) ----------------
__global__ void k_attdot(const float* __restrict__ att_s,
                         const float* __restrict__ att_d) {
    int gw = (blockIdx.x * blockDim.x + threadIdx.x) >> 5;
    int lane = threadIdx.x & 31;
    if (gw >= N_NODES) return;
    int head = lane >> 3, idx = lane & 7;
    int c = head * 32 + idx * 4;
    float4 hv = *(const float4*)&g_h[(size_t)gw * FDIM + c];
    float4 a1 = *(const float4*)&att_s[c];
    float4 a2 = *(const float4*)&att_d[c];
    float vs = hv.x * a1.x + hv.y * a1.y + hv.z * a1.z + hv.w * a1.w;
    float vd = hv.x * a2.x + hv.y * a2.y + hv.z * a2.z + hv.w * a2.w;
    vs += __shfl_down_sync(0xffffffffu, vs, 4);
    vs += __shfl_down_sync(0xffffffffu, vs, 2);
    vs += __shfl_down_sync(0xffffffffu, vs, 1);
    vd += __shfl_down_sync(0xffffffffu, vd, 4);
    vd += __shfl_down_sync(0xffffffffu, vd, 2);
    vd += __shfl_down_sync(0xffffffffu, vd, 1);
    if (idx == 0) {
        g_asrc[gw * HEADS + head] = vs;
        g_adst[gw * HEADS + head] = vd;
    }
}

// ---------------- segment softmax + weighted aggregation (warp per dst node) ----------------
// reads g_h + g_asrc/g_adst + CSR, writes g_buf = relu(agg + bias)
__global__ void k_aggregate(const float* __restrict__ bias) {
    int d = (blockIdx.x * blockDim.x + threadIdx.x) >> 5;
    int lane = threadIdx.x & 31;
    if (d >= N_NODES) return;
    int beg = g_off[d], end = g_off[d + 1];

    float4 adv = *(const float4*)&g_adst[d * HEADS];
    float ad0 = adv.x, ad1 = adv.y, ad2 = adv.z, ad3 = adv.w;

    // phase 1: per-head max over incoming edges
    float m0 = -1e30f, m1 = -1e30f, m2 = -1e30f, m3 = -1e30f;
    for (int j = beg + lane; j < end; j += 32) {
        int s = g_csrc[j];
        float4 as = *(const float4*)&g_asrc[s * HEADS];
        m0 = fmaxf(m0, lrelu(as.x + ad0));
        m1 = fmaxf(m1, lrelu(as.y + ad1));
        m2 = fmaxf(m2, lrelu(as.z + ad2));
        m3 = fmaxf(m3, lrelu(as.w + ad3));
    }
#pragma unroll
    for (int o = 16; o; o >>= 1) {
        m0 = fmaxf(m0, __shfl_xor_sync(0xffffffffu, m0, o));
        m1 = fmaxf(m1, __shfl_xor_sync(0xffffffffu, m1, o));
        m2 = fmaxf(m2, __shfl_xor_sync(0xffffffffu, m2, o));
        m3 = fmaxf(m3, __shfl_xor_sync(0xffffffffu, m3, o));
    }

    // phase 2: per-head sum of exp
    float s0 = 0.f, s1 = 0.f, s2 = 0.f, s3 = 0.f;
    for (int j = beg + lane; j < end; j += 32) {
        int s = g_csrc[j];
        float4 as = *(const float4*)&g_asrc[s * HEADS];
        s0 += __expf(lrelu(as.x + ad0) - m0);
        s1 += __expf(lrelu(as.y + ad1) - m1);
        s2 += __expf(lrelu(as.z + ad2) - m2);
        s3 += __expf(lrelu(as.w + ad3) - m3);
    }
#pragma unroll
    for (int o = 16; o; o >>= 1) {
        s0 += __shfl_xor_sync(0xffffffffu, s0, o);
        s1 += __shfl_xor_sync(0xffffffffu, s1, o);
        s2 += __shfl_xor_sync(0xffffffffu, s2, o);
        s3 += __shfl_xor_sync(0xffffffffu, s3, o);
    }

    // phase 3: weighted aggregation. lane owns channels [lane*4, lane*4+4) -> head = lane>>3
    int myh = lane >> 3;
    float mh  = (myh == 0) ? m0 : (myh == 1) ? m1 : (myh == 2) ? m2 : m3;
    float sh  = (myh == 0) ? s0 : (myh == 1) ? s1 : (myh == 2) ? s2 : s3;
    float adm = (myh == 0) ? ad0 : (myh == 1) ? ad1 : (myh == 2) ? ad2 : ad3;
    float inv = 1.f / sh;

    float4 acc = make_float4(0.f, 0.f, 0.f, 0.f);
    for (int j = beg; j < end; j++) {
        int s = g_csrc[j];
        float e = lrelu(g_asrc[s * HEADS + myh] + adm);
        float alpha = __expf(e - mh) * inv;
        float4 hv = *(const float4*)&g_h[(size_t)s * FDIM + lane * 4];
        acc.x = fmaf(alpha, hv.x, acc.x);
        acc.y = fmaf(alpha, hv.y, acc.y);
        acc.z = fmaf(alpha, hv.z, acc.z);
        acc.w = fmaf(alpha, hv.w, acc.w);
    }
    float4 b = *(const float4*)&bias[lane * 4];
    acc.x = fmaxf(acc.x + b.x, 0.f);
    acc.y = fmaxf(acc.y + b.y, 0.f);
    acc.z = fmaxf(acc.z + b.z, 0.f);
    acc.w = fmaxf(acc.w + b.w, 0.f);
    *(float4*)&g_buf[(size_t)d * FDIM + lane * 4] = acc;
}

// ---------------- global mean pool + linear head (reads g_buf) ----------------
__global__ void k_pool(const int* __restrict__ batch,
                       const float* __restrict__ w_lin,
                       const float* __restrict__ b_lin,
                       float* __restrict__ out) {
    int g = blockIdx.x;       // 64 blocks, 128 threads
    __shared__ int s_lo, s_hi;
    __shared__ float pooled[FDIM];
    if (threadIdx.x == 0) {
        int lo = 0, hi = N_NODES;
        while (lo < hi) { int mid = (lo + hi) >> 1; if (batch[mid] < g) lo = mid + 1; else hi = mid; }
        s_lo = lo;
        hi = N_NODES;
        while (lo < hi) { int mid = (lo + hi) >> 1; if (batch[mid] < g + 1) lo = mid + 1; else hi = mid; }
        s_hi = lo;
    }
    __syncthreads();
    int lo = s_lo, hi = s_hi;
    float s = 0.f;
    for (int n = lo; n < hi; n++) s += g_buf[(size_t)n * FDIM + threadIdx.x];
    float cnt = (float)(hi - lo);
    pooled[threadIdx.x] = s / fmaxf(cnt, 1.f);
    __syncthreads();
    if (threadIdx.x < OUT_CH) {
        float acc = b_lin[threadIdx.x];
        for (int c = 0; c < FDIM; c++) acc += pooled[c] * w_lin[c * OUT_CH + threadIdx.x];
        out[g * OUT_CH + threadIdx.x] = acc;
    }
}

// ---------------- launch ----------------
extern "C" void kernel_launch(void* const* d_in, const int* in_sizes, int n_in,
                              void* d_out, int out_size) {
    const float* x      = (const float*)d_in[0];
    const int*   ei     = (const int*)d_in[1];     // int32 (JAX default: x64 disabled)
    const int*   batch  = (const int*)d_in[2];     // int32
    const float* W1     = (const float*)d_in[3];
    const float* att_s1 = (const float*)d_in[4];
    const float* att_d1 = (const float*)d_in[5];
    const float* b1     = (const float*)d_in[6];
    const float* W2     = (const float*)d_in[7];
    const float* att_s2 = (const float*)d_in[8];
    const float* att_d2 = (const float*)d_in[9];
    const float* b2     = (const float*)d_in[10];
    const float* w_lin  = (const float*)d_in[11];
    const float* b_lin  = (const float*)d_in[12];
    float* out = (float*)d_out;

    const int EB = (ET + 255) / 256;
    const int NB = (N_NODES + 255) / 256;
    const int WB = (N_NODES * 32 + 255) / 256;   // warp-per-node grids
    const int GB = (N_NODES + 63) / 64;          // gemm tiles

    // CSR build (per launch, deterministic)
    k_zero_counts<<<NB, 256>>>();
    k_hist<<<EB, 256>>>(ei);
    k_scan<<<1, 1024>>>();
    k_scatter<<<EB, 256>>>(ei);

    // layer 1
    k_gemm<<<GB, 256>>>(x, W1);
    k_attdot<<<WB, 256>>>(att_s1, att_d1);
    k_aggregate<<<WB, 256>>>(b1);

    // layer 2
    k_gemm<<<GB, 256>>>(nullptr, W2);
    k_attdot<<<WB, 256>>>(att_s2, att_d2);
    k_aggregate<<<WB, 256>>>(b2);

    // pool + linear
    k_pool<<<N_GRAPHS, 128>>>(batch, w_lin, b_lin, out);
}

// round 4
// speedup vs baseline: 1.1811x; 1.1811x over previous
#include <cuda_runtime.h>

#define N_NODES 50000
#define N_EDGES 800000
#define ET (N_EDGES + N_NODES)   // with self loops
#define FDIM 128
#define HEADS 4
#define HID 32
#define N_GRAPHS 64
#define OUT_CH 10
#define NEG 0.2f

#define GEMM_BLOCKS ((N_NODES + 127) / 128)          // 391
#define HIST_BLOCKS ((ET + 255) / 256)               // 3321
#define ATT_BLOCKS  ((N_NODES * 32 + 255) / 256)     // 6250

// ---------------- scratch (static device globals; allocation-free) ----------------
__device__ float g_h[(size_t)N_NODES * FDIM];     // GEMM output (pre-activation h)
__device__ float g_buf[(size_t)N_NODES * FDIM];   // layer output (post relu+bias)
__device__ float g_asrc[N_NODES * HEADS];
__device__ float g_adst[N_NODES * HEADS];
__device__ int   g_counts[N_NODES];
__device__ int   g_off[N_NODES + 1];
__device__ int   g_cur[N_NODES];
__device__ int   g_csrc[ET];

__device__ __forceinline__ float lrelu(float x) { return x > 0.f ? x : NEG * x; }

// ---------------- zero counts ----------------
__global__ void k_zero_counts() {
    int i = blockIdx.x * blockDim.x + threadIdx.x;
    if (i < N_NODES) g_counts[i] = 0;
}

// ---------------- fused GEMM (128x128 tile, 8x8 micro) + degree histogram ----------------
// blocks [0, GEMM_BLOCKS): g_h[N,128] = X @ W   (X = Xext ? Xext : g_buf)
// blocks [GEMM_BLOCKS, +HIST_BLOCKS): histogram of dst (only when ei != null)
__global__ void __launch_bounds__(256) k_gemm_hist(const float* __restrict__ Xext,
                                                   const float* __restrict__ W,
                                                   const int* __restrict__ ei) {
    if (blockIdx.x >= GEMM_BLOCKS) {
        if (ei) {
            int i = (blockIdx.x - GEMM_BLOCKS) * 256 + threadIdx.x;
            if (i < ET) {
                int d = (i < N_EDGES) ? ei[N_EDGES + i] : (i - N_EDGES);
                atomicAdd(&g_counts[d], 1);
            }
        }
        return;
    }
    const float* X = Xext ? Xext : (const float*)g_buf;
    __shared__ float xs[32][132];   // transposed: xs[k][row]
    __shared__ float ws[32][132];   // ws[k][col]
    const int tid = threadIdx.x;
    const int ty = tid >> 4, tx = tid & 15;
    const int row0 = blockIdx.x * 128;

    float acc[8][8];
#pragma unroll
    for (int i = 0; i < 8; i++)
#pragma unroll
        for (int j = 0; j < 8; j++) acc[i][j] = 0.f;

    for (int kt = 0; kt < 128; kt += 32) {
        // load X tile (128 rows x 32 k), store transposed
        {
            int c0 = (tid & 7) * 4;
#pragma unroll
            for (int it = 0; it < 4; it++) {
                int r = (tid >> 3) + it * 32;
                int gr = row0 + r;
                float4 v = make_float4(0.f, 0.f, 0.f, 0.f);
                if (gr < N_NODES) v = *(const float4*)&X[(size_t)gr * FDIM + kt + c0];
                xs[c0 + 0][r] = v.x; xs[c0 + 1][r] = v.y;
                xs[c0 + 2][r] = v.z; xs[c0 + 3][r] = v.w;
            }
        }
        // load W tile (32 k x 128 cols)
        {
            int c = (tid & 31) * 4;
#pragma unroll
            for (int it = 0; it < 4; it++) {
                int k = (tid >> 5) + it * 8;
                *(float4*)&ws[k][c] = *(const float4*)&W[(size_t)(kt + k) * FDIM + c];
            }
        }
        __syncthreads();
#pragma unroll
        for (int k = 0; k < 32; k++) {
            float4 a0 = *(const float4*)&xs[k][ty * 8];
            float4 a1 = *(const float4*)&xs[k][ty * 8 + 4];
            float4 b0 = *(const float4*)&ws[k][tx * 8];
            float4 b1 = *(const float4*)&ws[k][tx * 8 + 4];
            float av[8] = {a0.x, a0.y, a0.z, a0.w, a1.x, a1.y, a1.z, a1.w};
            float bv[8] = {b0.x, b0.y, b0.z, b0.w, b1.x, b1.y, b1.z, b1.w};
#pragma unroll
            for (int i = 0; i < 8; i++)
#pragma unroll
                for (int j = 0; j < 8; j++) acc[i][j] = fmaf(av[i], bv[j], acc[i][j]);
        }
        __syncthreads();
    }
#pragma unroll
    for (int i = 0; i < 8; i++) {
        int gr = row0 + ty * 8 + i;
        if (gr < N_NODES) {
            float4* dst = (float4*)&g_h[(size_t)gr * FDIM + tx * 8];
            dst[0] = make_float4(acc[i][0], acc[i][1], acc[i][2], acc[i][3]);
            dst[1] = make_float4(acc[i][4], acc[i][5], acc[i][6], acc[i][7]);
        }
    }
}

// ---------------- offsets scan (single block) ----------------
__global__ void k_scan() {
    __shared__ int part[1024];
    int tid = threadIdx.x;
    const int PER = (N_NODES + 1023) / 1024;   // 49
    int base = tid * PER;
    int s = 0;
    for (int i = 0; i < PER; i++) {
        int idx = base + i;
        if (idx < N_NODES) s += g_counts[idx];
    }
    part[tid] = s;
    __syncthreads();
    for (int off = 1; off < 1024; off <<= 1) {
        int v = (tid >= off) ? part[tid - off] : 0;
        __syncthreads();
        part[tid] += v;
        __syncthreads();
    }
    int run = (tid > 0) ? part[tid - 1] : 0;
    for (int i = 0; i < PER; i++) {
        int idx = base + i;
        if (idx < N_NODES) {
            g_off[idx] = run;
            g_cur[idx] = run;
            run += g_counts[idx];
        }
    }
    if (tid == 1023) g_off[N_NODES] = part[1023];
}

// ---------------- fused attdot (warp per node) + CSR scatter ----------------
__global__ void k_attdot_scatter(const float* __restrict__ att_s,
                                 const float* __restrict__ att_d,
                                 const int* __restrict__ ei) {
    if (blockIdx.x >= ATT_BLOCKS) {
        if (ei) {
            int i = (blockIdx.x - ATT_BLOCKS) * 256 + threadIdx.x;
            if (i < ET) {
                int s, d;
                if (i < N_EDGES) { s = ei[i]; d = ei[N_EDGES + i]; }
                else             { s = i - N_EDGES; d = s; }
                int pos = atomicAdd(&g_cur[d], 1);
                g_csrc[pos] = s;
            }
        }
        return;
    }
    int gw = (blockIdx.x * 256 + threadIdx.x) >> 5;
    int lane = threadIdx.x & 31;
    if (gw >= N_NODES) return;
    int head = lane >> 3, idx = lane & 7;
    int c = head * 32 + idx * 4;
    float4 hv = *(const float4*)&g_h[(size_t)gw * FDIM + c];
    float4 a1 = *(const float4*)&att_s[c];
    float4 a2 = *(const float4*)&att_d[c];
    float vs = hv.x * a1.x + hv.y * a1.y + hv.z * a1.z + hv.w * a1.w;
    float vd = hv.x * a2.x + hv.y * a2.y + hv.z * a2.z + hv.w * a2.w;
    vs += __shfl_down_sync(0xffffffffu, vs, 4);
    vs += __shfl_down_sync(0xffffffffu, vs, 2);
    vs += __shfl_down_sync(0xffffffffu, vs, 1);
    vd += __shfl_down_sync(0xffffffffu, vd, 4);
    vd += __shfl_down_sync(0xffffffffu, vd, 2);
    vd += __shfl_down_sync(0xffffffffu, vd, 1);
    if (idx == 0) {
        g_asrc[gw * HEADS + head] = vs;
        g_adst[gw * HEADS + head] = vd;
    }
}

// ---------------- segment softmax + weighted aggregation (warp per dst node) ----------------
__global__ void __launch_bounds__(256) k_aggregate(const float* __restrict__ bias) {
    int d = (blockIdx.x * 256 + threadIdx.x) >> 5;
    int lane = threadIdx.x & 31;
    if (d >= N_NODES) return;
    const int beg = g_off[d], end = g_off[d + 1];

    float4 adv = *(const float4*)&g_adst[d * HEADS];
    const float ad0 = adv.x, ad1 = adv.y, ad2 = adv.z, ad3 = adv.w;

    // single gather pass: cache up to 2 e-values per lane per head (covers deg <= 64)
    float ea0, ea1, ea2, ea3, eb0, eb1, eb2, eb3;
    float m0 = -1e30f, m1 = -1e30f, m2 = -1e30f, m3 = -1e30f;
    int B = 0;
    for (int j = beg + lane; j < end; j += 32) {
        int s = g_csrc[j];
        float4 as = *(const float4*)&g_asrc[s * HEADS];
        float v0 = lrelu(as.x + ad0), v1 = lrelu(as.y + ad1);
        float v2 = lrelu(as.z + ad2), v3 = lrelu(as.w + ad3);
        if (B == 0)      { ea0 = v0; ea1 = v1; ea2 = v2; ea3 = v3; }
        else if (B == 1) { eb0 = v0; eb1 = v1; eb2 = v2; eb3 = v3; }
        m0 = fmaxf(m0, v0); m1 = fmaxf(m1, v1);
        m2 = fmaxf(m2, v2); m3 = fmaxf(m3, v3);
        B++;
    }
    // warp max
#pragma unroll
    for (int o = 16; o; o >>= 1) {
        m0 = fmaxf(m0, __shfl_xor_sync(0xffffffffu, m0, o));
        m1 = fmaxf(m1, __shfl_xor_sync(0xffffffffu, m1, o));
        m2 = fmaxf(m2, __shfl_xor_sync(0xffffffffu, m2, o));
        m3 = fmaxf(m3, __shfl_xor_sync(0xffffffffu, m3, o));
    }
    // exp-sums from cached values (+rare overflow recompute)
    float s0 = 0.f, s1 = 0.f, s2 = 0.f, s3 = 0.f;
    if (B >= 1) {
        s0 += __expf(ea0 - m0); s1 += __expf(ea1 - m1);
        s2 += __expf(ea2 - m2); s3 += __expf(ea3 - m3);
    }
    if (B >= 2) {
        s0 += __expf(eb0 - m0); s1 += __expf(eb1 - m1);
        s2 += __expf(eb2 - m2); s3 += __expf(eb3 - m3);
    }
    for (int j = beg + lane + 64; j < end; j += 32) {   // deg > 64 fallback
        int s = g_csrc[j];
        float4 as = *(const float4*)&g_asrc[s * HEADS];
        s0 += __expf(lrelu(as.x + ad0) - m0);
        s1 += __expf(lrelu(as.y + ad1) - m1);
        s2 += __expf(lrelu(as.z + ad2) - m2);
        s3 += __expf(lrelu(as.w + ad3) - m3);
    }
#pragma unroll
    for (int o = 16; o; o >>= 1) {
        s0 += __shfl_xor_sync(0xffffffffu, s0, o);
        s1 += __shfl_xor_sync(0xffffffffu, s1, o);
        s2 += __shfl_xor_sync(0xffffffffu, s2, o);
        s3 += __shfl_xor_sync(0xffffffffu, s3, o);
    }

    // lane owns channels [lane*4, lane*4+4) -> head = lane>>3
    const int myh = lane >> 3;
    const float mh  = (myh == 0) ? m0 : (myh == 1) ? m1 : (myh == 2) ? m2 : m3;
    const float sh  = (myh == 0) ? s0 : (myh == 1) ? s1 : (myh == 2) ? s2 : s3;
    const float adm = (myh == 0) ? ad0 : (myh == 1) ? ad1 : (myh == 2) ? ad2 : ad3;
    const float inv = 1.f / sh;
    const float* __restrict__ asr = (const float*)g_asrc;
    const float* __restrict__ H   = (const float*)g_h;
    const int ch = lane * 4;

    // phase 3: weighted aggregation, unrolled x4 for MLP
    float4 acc0 = make_float4(0.f, 0.f, 0.f, 0.f);
    float4 acc1 = make_float4(0.f, 0.f, 0.f, 0.f);
    int j = beg;
    for (; j + 4 <= end; j += 4) {
        int sA = g_csrc[j], sB = g_csrc[j + 1], sC = g_csrc[j + 2], sD = g_csrc[j + 3];
        float aA = asr[sA * HEADS + myh], aB = asr[sB * HEADS + myh];
        float aC = asr[sC * HEADS + myh], aD = asr[sD * HEADS + myh];
        float4 hA = *(const float4*)&H[(size_t)sA * FDIM + ch];
        float4 hB = *(const float4*)&H[(size_t)sB * FDIM + ch];
        float4 hC = *(const float4*)&H[(size_t)sC * FDIM + ch];
        float4 hD = *(const float4*)&H[(size_t)sD * FDIM + ch];
        float alA = __expf(lrelu(aA + adm) - mh) * inv;
        float alB = __expf(lrelu(aB + adm) - mh) * inv;
        float alC = __expf(lrelu(aC + adm) - mh) * inv;
        float alD = __expf(lrelu(aD + adm) - mh) * inv;
        acc0.x = fmaf(alA, hA.x, acc0.x); acc0.y = fmaf(alA, hA.y, acc0.y);
        acc0.z = fmaf(alA, hA.z, acc0.z); acc0.w = fmaf(alA, hA.w, acc0.w);
        acc1.x = fmaf(alB, hB.x, acc1.x); acc1.y = fmaf(alB, hB.y, acc1.y);
        acc1.z = fmaf(alB, hB.z, acc1.z); acc1.w = fmaf(alB, hB.w, acc1.w);
        acc0.x = fmaf(alC, hC.x, acc0.x); acc0.y = fmaf(alC, hC.y, acc0.y);
        acc0.z = fmaf(alC, hC.z, acc0.z); acc0.w = fmaf(alC, hC.w, acc0.w);
        acc1.x = fmaf(alD, hD.x, acc1.x); acc1.y = fmaf(alD, hD.y, acc1.y);
        acc1.z = fmaf(alD, hD.z, acc1.z); acc1.w = fmaf(alD, hD.w, acc1.w);
    }
    for (; j < end; j++) {
        int s = g_csrc[j];
        float a = asr[s * HEADS + myh];
        float4 hv = *(const float4*)&H[(size_t)s * FDIM + ch];
        float al = __expf(lrelu(a + adm) - mh) * inv;
        acc0.x = fmaf(al, hv.x, acc0.x); acc0.y = fmaf(al, hv.y, acc0.y);
        acc0.z = fmaf(al, hv.z, acc0.z); acc0.w = fmaf(al, hv.w, acc0.w);
    }
    float4 b = *(const float4*)&bias[ch];
    float4 r;
    r.x = fmaxf(acc0.x + acc1.x + b.x, 0.f);
    r.y = fmaxf(acc0.y + acc1.y + b.y, 0.f);
    r.z = fmaxf(acc0.z + acc1.z + b.z, 0.f);
    r.w = fmaxf(acc0.w + acc1.w + b.w, 0.f);
    *(float4*)&g_buf[(size_t)d * FDIM + ch] = r;
}

// ---------------- global mean pool + linear head (reads g_buf) ----------------
__global__ void k_pool(const int* __restrict__ batch,
                       const float* __restrict__ w_lin,
                       const float* __restrict__ b_lin,
                       float* __restrict__ out) {
    int g = blockIdx.x;       // 64 blocks, 128 threads
    __shared__ int s_lo, s_hi;
    __shared__ float pooled[FDIM];
    if (threadIdx.x == 0) {
        int lo = 0, hi = N_NODES;
        while (lo < hi) { int mid = (lo + hi) >> 1; if (batch[mid] < g) lo = mid + 1; else hi = mid; }
        s_lo = lo;
        hi = N_NODES;
        while (lo < hi) { int mid = (lo + hi) >> 1; if (batch[mid] < g + 1) lo = mid + 1; else hi = mid; }
        s_hi = lo;
    }
    __syncthreads();
    int lo = s_lo, hi = s_hi;
    float a0 = 0.f, a1 = 0.f, a2 = 0.f, a3 = 0.f;
    int n = lo;
    for (; n + 4 <= hi; n += 4) {
        a0 += g_buf[(size_t)(n + 0) * FDIM + threadIdx.x];
        a1 += g_buf[(size_t)(n + 1) * FDIM + threadIdx.x];
        a2 += g_buf[(size_t)(n + 2) * FDIM + threadIdx.x];
        a3 += g_buf[(size_t)(n + 3) * FDIM + threadIdx.x];
    }
    for (; n < hi; n++) a0 += g_buf[(size_t)n * FDIM + threadIdx.x];
    float cnt = (float)(hi - lo);
    pooled[threadIdx.x] = (a0 + a1 + a2 + a3) / fmaxf(cnt, 1.f);
    __syncthreads();
    if (threadIdx.x < OUT_CH) {
        float acc = b_lin[threadIdx.x];
        for (int c = 0; c < FDIM; c++) acc += pooled[c] * w_lin[c * OUT_CH + threadIdx.x];
        out[g * OUT_CH + threadIdx.x] = acc;
    }
}

// ---------------- launch ----------------
extern "C" void kernel_launch(void* const* d_in, const int* in_sizes, int n_in,
                              void* d_out, int out_size) {
    const float* x      = (const float*)d_in[0];
    const int*   ei     = (const int*)d_in[1];
    const int*   batch  = (const int*)d_in[2];
    const float* W1     = (const float*)d_in[3];
    const float* att_s1 = (const float*)d_in[4];
    const float* att_d1 = (const float*)d_in[5];
    const float* b1     = (const float*)d_in[6];
    const float* W2     = (const float*)d_in[7];
    const float* att_s2 = (const float*)d_in[8];
    const float* att_d2 = (const float*)d_in[9];
    const float* b2     = (const float*)d_in[10];
    const float* w_lin  = (const float*)d_in[11];
    const float* b_lin  = (const float*)d_in[12];
    float* out = (float*)d_out;

    const int NB = (N_NODES + 255) / 256;
    const int WB = (N_NODES * 32 + 255) / 256;

    k_zero_counts<<<NB, 256>>>();

    // layer 1 (GEMM overlapped with hist; attdot overlapped with scatter)
    k_gemm_hist<<<GEMM_BLOCKS + HIST_BLOCKS, 256>>>(x, W1, ei);
    k_scan<<<1, 1024>>>();
    k_attdot_scatter<<<ATT_BLOCKS + HIST_BLOCKS, 256>>>(att_s1, att_d1, ei);
    k_aggregate<<<WB, 256>>>(b1);

    // layer 2 (CSR already built)
    k_gemm_hist<<<GEMM_BLOCKS, 256>>>(nullptr, W2, nullptr);
    k_attdot_scatter<<<ATT_BLOCKS, 256>>>(att_s2, att_d2, nullptr);
    k_aggregate<<<WB, 256>>>(b2);

    k_pool<<<N_GRAPHS, 128>>>(batch, w_lin, b_lin, out);
}

// round 6
// speedup vs baseline: 1.3516x; 1.1443x over previous
#include <cuda_runtime.h>
#include <cstdint>

#define N_NODES 50000
#define N_EDGES 800000
#define ET (N_EDGES + N_NODES)
#define FDIM 128
#define HEADS 4
#define N_GRAPHS 64
#define OUT_CH 10
#define NEG 0.2f

#define GEMM_BLOCKS ((N_NODES + 127) / 128)        // 391
#define ATT_BLOCKS  ((N_NODES * 32 + 255) / 256)   // 6250
#define SCAT_BLOCKS ((ET + 255) / 256)

// SMEM for mma GEMM: As[128][68] + Bs[64][136] (uint32 tf32 bits)
#define AS_STRIDE 68
#define BS_STRIDE 136
#define AS_WORDS (128 * AS_STRIDE)
#define SMEM_WORDS (AS_WORDS + 64 * BS_STRIDE)

// ---------------- scratch ----------------
__device__ float g_h[(size_t)N_NODES * FDIM];
__device__ float g_buf[(size_t)N_NODES * FDIM];
__device__ float g_asrc[N_NODES * HEADS];
__device__ float g_adst[N_NODES * HEADS];
__device__ int   g_counts[N_NODES];
__device__ int   g_off[N_NODES + 1];
__device__ int   g_cur[N_NODES];
__device__ int   g_csrc[ET];

__device__ __forceinline__ float lrelu(float x) { return x > 0.f ? x : NEG * x; }
__device__ __forceinline__ uint32_t f2tf32(float f) {
    uint32_t r;
    asm("cvt.rna.tf32.f32 %0, %1;" : "=r"(r) : "f"(f));
    return r;
}
__device__ __forceinline__ void mma16n8k8(float* d, const uint32_t* a, uint32_t b0, uint32_t b1) {
    asm volatile(
        "mma.sync.aligned.m16n8k8.row.col.f32.tf32.tf32.f32 "
        "{%0,%1,%2,%3}, {%4,%5,%6,%7}, {%8,%9}, {%0,%1,%2,%3};"
        : "+f"(d[0]), "+f"(d[1]), "+f"(d[2]), "+f"(d[3])
        : "r"(a[0]), "r"(a[1]), "r"(a[2]), "r"(a[3]), "r"(b0), "r"(b1));
}

// ---------------- zero counts ----------------
__global__ void k_zero_counts() {
    int i = blockIdx.x * blockDim.x + threadIdx.x;
    if (i < N_NODES) g_counts[i] = 0;
}

// ---------------- degree histogram (grid-strided) ----------------
__global__ void k_hist(const int* __restrict__ ei) {
    for (int i = blockIdx.x * blockDim.x + threadIdx.x; i < ET; i += gridDim.x * blockDim.x) {
        int d = (i < N_EDGES) ? ei[N_EDGES + i] : (i - N_EDGES);
        atomicAdd(&g_counts[d], 1);
    }
}

// ---------------- tensor-core tf32 GEMM: g_h[N,128] = X @ W[128,128] ----------------
// block: 256 thr (8 warps), tile 128(M=nodes) x 128(N=features), K chunked 64.
// warp grid 4(M) x 2(N): warp tile 32x64 -> 2 m16 x 8 n8 mma tiles.
__global__ void __launch_bounds__(256) k_gemm(const float* __restrict__ Xext,
                                              const float* __restrict__ W) {
    extern __shared__ uint32_t sm[];
    uint32_t* As = sm;                 // [128][68]
    uint32_t* Bs = sm + AS_WORDS;      // [64][136]
    const float* X = Xext ? Xext : (const float*)g_buf;
    const int tid = threadIdx.x;
    const int wid = tid >> 5, lane = tid & 31;
    const int g = lane >> 2, t = lane & 3;
    const int wm = wid & 3, wn = wid >> 2;
    const int row0 = blockIdx.x * 128;

    float d[2][8][4];
#pragma unroll
    for (int mi = 0; mi < 2; mi++)
#pragma unroll
        for (int ni = 0; ni < 8; ni++)
#pragma unroll
            for (int k = 0; k < 4; k++) d[mi][ni][k] = 0.f;

    for (int kc = 0; kc < 128; kc += 64) {
        // load A chunk: 128 rows x 64 cols (16 float4-loads per row)
#pragma unroll
        for (int it = 0; it < 8; it++) {
            int idx = tid + it * 256;          // 0..2047
            int r = idx >> 4, c4 = (idx & 15) * 4;
            int gr = row0 + r;
            uint32_t o0 = 0, o1 = 0, o2 = 0, o3 = 0;
            if (gr < N_NODES) {
                float4 v = *(const float4*)&X[(size_t)gr * FDIM + kc + c4];
                o0 = f2tf32(v.x); o1 = f2tf32(v.y); o2 = f2tf32(v.z); o3 = f2tf32(v.w);
            }
            uint32_t* p = &As[r * AS_STRIDE + c4];
            p[0] = o0; p[1] = o1; p[2] = o2; p[3] = o3;
        }
        // load B chunk: W rows kc..kc+63, all 128 cols
#pragma unroll
        for (int it = 0; it < 8; it++) {
            int idx = tid + it * 256;          // 0..2047
            int k = idx >> 5, n4 = (idx & 31) * 4;
            float4 v = *(const float4*)&W[(size_t)(kc + k) * FDIM + n4];
            uint32_t* p = &Bs[k * BS_STRIDE + n4];
            p[0] = f2tf32(v.x); p[1] = f2tf32(v.y); p[2] = f2tf32(v.z); p[3] = f2tf32(v.w);
        }
        __syncthreads();

#pragma unroll
        for (int ks = 0; ks < 8; ks++) {
            const int k0 = ks * 8;
            uint32_t a[2][4];
#pragma unroll
            for (int mi = 0; mi < 2; mi++) {
                int rb = wm * 32 + mi * 16;
                a[mi][0] = As[(rb + g) * AS_STRIDE + k0 + t];
                a[mi][1] = As[(rb + g + 8) * AS_STRIDE + k0 + t];
                a[mi][2] = As[(rb + g) * AS_STRIDE + k0 + t + 4];
                a[mi][3] = As[(rb + g + 8) * AS_STRIDE + k0 + t + 4];
            }
#pragma unroll
            for (int ni = 0; ni < 8; ni++) {
                int nb = wn * 64 + ni * 8;
                uint32_t b0 = Bs[(k0 + t) * BS_STRIDE + nb + g];
                uint32_t b1 = Bs[(k0 + t + 4) * BS_STRIDE + nb + g];
                mma16n8k8(d[0][ni], a[0], b0, b1);
                mma16n8k8(d[1][ni], a[1], b0, b1);
            }
        }
        __syncthreads();
    }

    // epilogue: c0/c1 -> (row, 2t), (row, 2t+1); c2/c3 -> row+8
#pragma unroll
    for (int mi = 0; mi < 2; mi++) {
        int r0 = row0 + wm * 32 + mi * 16 + g;
        int r1 = r0 + 8;
#pragma unroll
        for (int ni = 0; ni < 8; ni++) {
            int col = wn * 64 + ni * 8 + t * 2;
            if (r0 < N_NODES) *(float2*)&g_h[(size_t)r0 * FDIM + col] = make_float2(d[mi][ni][0], d[mi][ni][1]);
            if (r1 < N_NODES) *(float2*)&g_h[(size_t)r1 * FDIM + col] = make_float2(d[mi][ni][2], d[mi][ni][3]);
        }
    }
}

// ---------------- offsets scan ----------------
__global__ void k_scan() {
    __shared__ int part[1024];
    int tid = threadIdx.x;
    const int PER = (N_NODES + 1023) / 1024;
    int base = tid * PER;
    int s = 0;
    for (int i = 0; i < PER; i++) {
        int idx = base + i;
        if (idx < N_NODES) s += g_counts[idx];
    }
    part[tid] = s;
    __syncthreads();
    for (int off = 1; off < 1024; off <<= 1) {
        int v = (tid >= off) ? part[tid - off] : 0;
        __syncthreads();
        part[tid] += v;
        __syncthreads();
    }
    int run = (tid > 0) ? part[tid - 1] : 0;
    for (int i = 0; i < PER; i++) {
        int idx = base + i;
        if (idx < N_NODES) {
            g_off[idx] = run;
            g_cur[idx] = run;
            run += g_counts[idx];
        }
    }
    if (tid == 1023) g_off[N_NODES] = part[1023];
}

// ---------------- fused attdot (warp per node) + CSR scatter ----------------
__global__ void k_attdot_scatter(const float* __restrict__ att_s,
                                 const float* __restrict__ att_d,
                                 const int* __restrict__ ei) {
    if (blockIdx.x >= ATT_BLOCKS) {
        if (ei) {
            int i = (blockIdx.x - ATT_BLOCKS) * 256 + threadIdx.x;
            if (i < ET) {
                int s, d;
                if (i < N_EDGES) { s = ei[i]; d = ei[N_EDGES + i]; }
                else             { s = i - N_EDGES; d = s; }
                int pos = atomicAdd(&g_cur[d], 1);
                g_csrc[pos] = s;
            }
        }
        return;
    }
    int gw = (blockIdx.x * 256 + threadIdx.x) >> 5;
    int lane = threadIdx.x & 31;
    if (gw >= N_NODES) return;
    int head = lane >> 3, idx = lane & 7;
    int c = head * 32 + idx * 4;
    float4 hv = *(const float4*)&g_h[(size_t)gw * FDIM + c];
    float4 a1 = *(const float4*)&att_s[c];
    float4 a2 = *(const float4*)&att_d[c];
    float vs = hv.x * a1.x + hv.y * a1.y + hv.z * a1.z + hv.w * a1.w;
    float vd = hv.x * a2.x + hv.y * a2.y + hv.z * a2.z + hv.w * a2.w;
    vs += __shfl_down_sync(0xffffffffu, vs, 4);
    vs += __shfl_down_sync(0xffffffffu, vs, 2);
    vs += __shfl_down_sync(0xffffffffu, vs, 1);
    vd += __shfl_down_sync(0xffffffffu, vd, 4);
    vd += __shfl_down_sync(0xffffffffu, vd, 2);
    vd += __shfl_down_sync(0xffffffffu, vd, 1);
    if (idx == 0) {
        g_asrc[gw * HEADS + head] = vs;
        g_adst[gw * HEADS + head] = vd;
    }
}

// ---------------- segment softmax + weighted aggregation (warp per dst node) ----------------
__global__ void __launch_bounds__(256) k_aggregate(const float* __restrict__ bias) {
    int d = (blockIdx.x * 256 + threadIdx.x) >> 5;
    int lane = threadIdx.x & 31;
    if (d >= N_NODES) return;
    const int beg = g_off[d], end = g_off[d + 1];

    float4 adv = *(const float4*)&g_adst[d * HEADS];
    const float ad0 = adv.x, ad1 = adv.y, ad2 = adv.z, ad3 = adv.w;

    float ea0, ea1, ea2, ea3, eb0, eb1, eb2, eb3;
    float m0 = -1e30f, m1 = -1e30f, m2 = -1e30f, m3 = -1e30f;
    int B = 0;
    for (int j = beg + lane; j < end; j += 32) {
        int s = g_csrc[j];
        float4 as = *(const float4*)&g_asrc[s * HEADS];
        float v0 = lrelu(as.x + ad0), v1 = lrelu(as.y + ad1);
        float v2 = lrelu(as.z + ad2), v3 = lrelu(as.w + ad3);
        if (B == 0)      { ea0 = v0; ea1 = v1; ea2 = v2; ea3 = v3; }
        else if (B == 1) { eb0 = v0; eb1 = v1; eb2 = v2; eb3 = v3; }
        m0 = fmaxf(m0, v0); m1 = fmaxf(m1, v1);
        m2 = fmaxf(m2, v2); m3 = fmaxf(m3, v3);
        B++;
    }
#pragma unroll
    for (int o = 16; o; o >>= 1) {
        m0 = fmaxf(m0, __shfl_xor_sync(0xffffffffu, m0, o));
        m1 = fmaxf(m1, __shfl_xor_sync(0xffffffffu, m1, o));
        m2 = fmaxf(m2, __shfl_xor_sync(0xffffffffu, m2, o));
        m3 = fmaxf(m3, __shfl_xor_sync(0xffffffffu, m3, o));
    }
    float s0 = 0.f, s1 = 0.f, s2 = 0.f, s3 = 0.f;
    if (B >= 1) {
        s0 += __expf(ea0 - m0); s1 += __expf(ea1 - m1);
        s2 += __expf(ea2 - m2); s3 += __expf(ea3 - m3);
    }
    if (B >= 2) {
        s0 += __expf(eb0 - m0); s1 += __expf(eb1 - m1);
        s2 += __expf(eb2 - m2); s3 += __expf(eb3 - m3);
    }
    for (int j = beg + lane + 64; j < end; j += 32) {
        int s = g_csrc[j];
        float4 as = *(const float4*)&g_asrc[s * HEADS];
        s0 += __expf(lrelu(as.x + ad0) - m0);
        s1 += __expf(lrelu(as.y + ad1) - m1);
        s2 += __expf(lrelu(as.z + ad2) - m2);
        s3 += __expf(lrelu(as.w + ad3) - m3);
    }
#pragma unroll
    for (int o = 16; o; o >>= 1) {
        s0 += __shfl_xor_sync(0xffffffffu, s0, o);
        s1 += __shfl_xor_sync(0xffffffffu, s1, o);
        s2 += __shfl_xor_sync(0xffffffffu, s2, o);
        s3 += __shfl_xor_sync(0xffffffffu, s3, o);
    }

    const int myh = lane >> 3;
    const float mh  = (myh == 0) ? m0 : (myh == 1) ? m1 : (myh == 2) ? m2 : m3;
    const float sh  = (myh == 0) ? s0 : (myh == 1) ? s1 : (myh == 2) ? s2 : s3;
    const float adm = (myh == 0) ? ad0 : (myh == 1) ? ad1 : (myh == 2) ? ad2 : ad3;
    const float inv = 1.f / sh;
    const float* __restrict__ asr = (const float*)g_asrc;
    const float* __restrict__ H   = (const float*)g_h;
    const int ch = lane * 4;

    float4 acc0 = make_float4(0.f, 0.f, 0.f, 0.f);
    float4 acc1 = make_float4(0.f, 0.f, 0.f, 0.f);
    int j = beg;
    for (; j + 4 <= end; j += 4) {
        int sA = g_csrc[j], sB = g_csrc[j + 1], sC = g_csrc[j + 2], sD = g_csrc[j + 3];
        float aA = asr[sA * HEADS + myh], aB = asr[sB * HEADS + myh];
        float aC = asr[sC * HEADS + myh], aD = asr[sD * HEADS + myh];
        float4 hA = *(const float4*)&H[(size_t)sA * FDIM + ch];
        float4 hB = *(const float4*)&H[(size_t)sB * FDIM + ch];
        float4 hC = *(const float4*)&H[(size_t)sC * FDIM + ch];
        float4 hD = *(const float4*)&H[(size_t)sD * FDIM + ch];
        float alA = __expf(lrelu(aA + adm) - mh) * inv;
        float alB = __expf(lrelu(aB + adm) - mh) * inv;
        float alC = __expf(lrelu(aC + adm) - mh) * inv;
        float alD = __expf(lrelu(aD + adm) - mh) * inv;
        acc0.x = fmaf(alA, hA.x, acc0.x); acc0.y = fmaf(alA, hA.y, acc0.y);
        acc0.z = fmaf(alA, hA.z, acc0.z); acc0.w = fmaf(alA, hA.w, acc0.w);
        acc1.x = fmaf(alB, hB.x, acc1.x); acc1.y = fmaf(alB, hB.y, acc1.y);
        acc1.z = fmaf(alB, hB.z, acc1.z); acc1.w = fmaf(alB, hB.w, acc1.w);
        acc0.x = fmaf(alC, hC.x, acc0.x); acc0.y = fmaf(alC, hC.y, acc0.y);
        acc0.z = fmaf(alC, hC.z, acc0.z); acc0.w = fmaf(alC, hC.w, acc0.w);
        acc1.x = fmaf(alD, hD.x, acc1.x); acc1.y = fmaf(alD, hD.y, acc1.y);
        acc1.z = fmaf(alD, hD.z, acc1.z); acc1.w = fmaf(alD, hD.w, acc1.w);
    }
    for (; j < end; j++) {
        int s = g_csrc[j];
        float a = asr[s * HEADS + myh];
        float4 hv = *(const float4*)&H[(size_t)s * FDIM + ch];
        float al = __expf(lrelu(a + adm) - mh) * inv;
        acc0.x = fmaf(al, hv.x, acc0.x); acc0.y = fmaf(al, hv.y, acc0.y);
        acc0.z = fmaf(al, hv.z, acc0.z); acc0.w = fmaf(al, hv.w, acc0.w);
    }
    float4 b = *(const float4*)&bias[ch];
    float4 r;
    r.x = fmaxf(acc0.x + acc1.x + b.x, 0.f);
    r.y = fmaxf(acc0.y + acc1.y + b.y, 0.f);
    r.z = fmaxf(acc0.z + acc1.z + b.z, 0.f);
    r.w = fmaxf(acc0.w + acc1.w + b.w, 0.f);
    *(float4*)&g_buf[(size_t)d * FDIM + ch] = r;
}

// ---------------- global mean pool + linear head ----------------
__global__ void k_pool(const int* __restrict__ batch,
                       const float* __restrict__ w_lin,
                       const float* __restrict__ b_lin,
                       float* __restrict__ out) {
    int g = blockIdx.x;
    __shared__ int s_lo, s_hi;
    __shared__ float pooled[FDIM];
    if (threadIdx.x == 0) {
        int lo = 0, hi = N_NODES;
        while (lo < hi) { int mid = (lo + hi) >> 1; if (batch[mid] < g) lo = mid + 1; else hi = mid; }
        s_lo = lo;
        hi = N_NODES;
        while (lo < hi) { int mid = (lo + hi) >> 1; if (batch[mid] < g + 1) lo = mid + 1; else hi = mid; }
        s_hi = lo;
    }
    __syncthreads();
    int lo = s_lo, hi = s_hi;
    float a0 = 0.f, a1 = 0.f, a2 = 0.f, a3 = 0.f;
    int n = lo;
    for (; n + 4 <= hi; n += 4) {
        a0 += g_buf[(size_t)(n + 0) * FDIM + threadIdx.x];
        a1 += g_buf[(size_t)(n + 1) * FDIM + threadIdx.x];
        a2 += g_buf[(size_t)(n + 2) * FDIM + threadIdx.x];
        a3 += g_buf[(size_t)(n + 3) * FDIM + threadIdx.x];
    }
    for (; n < hi; n++) a0 += g_buf[(size_t)n * FDIM + threadIdx.x];
    float cnt = (float)(hi - lo);
    pooled[threadIdx.x] = (a0 + a1 + a2 + a3) / fmaxf(cnt, 1.f);
    __syncthreads();
    if (threadIdx.x < OUT_CH) {
        float acc = b_lin[threadIdx.x];
        for (int c = 0; c < FDIM; c++) acc += pooled[c] * w_lin[c * OUT_CH + threadIdx.x];
        out[g * OUT_CH + threadIdx.x] = acc;
    }
}

// ---------------- launch ----------------
extern "C" void kernel_launch(void* const* d_in, const int* in_sizes, int n_in,
                              void* d_out, int out_size) {
    const float* x      = (const float*)d_in[0];
    const int*   ei     = (const int*)d_in[1];
    const int*   batch  = (const int*)d_in[2];
    const float* W1     = (const float*)d_in[3];
    const float* att_s1 = (const float*)d_in[4];
    const float* att_d1 = (const float*)d_in[5];
    const float* b1     = (const float*)d_in[6];
    const float* W2     = (const float*)d_in[7];
    const float* att_s2 = (const float*)d_in[8];
    const float* att_d2 = (const float*)d_in[9];
    const float* b2     = (const float*)d_in[10];
    const float* w_lin  = (const float*)d_in[11];
    const float* b_lin  = (const float*)d_in[12];
    float* out = (float*)d_out;

    const int SMEM_BYTES = SMEM_WORDS * 4;   // ~70KB
    cudaFuncSetAttribute(k_gemm, cudaFuncAttributeMaxDynamicSharedMemorySize, SMEM_BYTES);

    const int NB = (N_NODES + 255) / 256;
    const int WB = (N_NODES * 32 + 255) / 256;

    k_zero_counts<<<NB, 256>>>();
    k_hist<<<296, 256>>>(ei);

    // layer 1
    k_gemm<<<GEMM_BLOCKS, 256, SMEM_BYTES>>>(x, W1);
    k_scan<<<1, 1024>>>();
    k_attdot_scatter<<<ATT_BLOCKS + SCAT_BLOCKS, 256>>>(att_s1, att_d1, ei);
    k_aggregate<<<WB, 256>>>(b1);

    // layer 2
    k_gemm<<<GEMM_BLOCKS, 256, SMEM_BYTES>>>(nullptr, W2);
    k_attdot_scatter<<<ATT_BLOCKS, 256>>>(att_s2, att_d2, nullptr);
    k_aggregate<<<WB, 256>>>(b2);

    k_pool<<<N_GRAPHS, 128>>>(batch, w_lin, b_lin, out);
}

// round 7
// speedup vs baseline: 1.7252x; 1.2764x over previous
#include <cuda_runtime.h>
#include <cstdint>

#define N_NODES 50000
#define N_EDGES 800000
#define ET (N_EDGES + N_NODES)
#define FDIM 128
#define HEADS 4
#define N_GRAPHS 64
#define OUT_CH 10
#define NEG 0.2f

#define GEMM_BLOCKS ((N_NODES + 127) / 128)        // 391
#define ATT_BLOCKS  ((N_NODES * 32 + 255) / 256)   // 6250
#define SCAT_BLOCKS ((ET + 255) / 256)
#define SCAN_BLOCKS ((N_NODES + 1023) / 1024)      // 49

// SMEM for mma GEMM: As[128][68] + Bs[64][136] (uint32 tf32 bits)
#define AS_STRIDE 68
#define BS_STRIDE 136
#define AS_WORDS (128 * AS_STRIDE)
#define SMEM_WORDS (AS_WORDS + 64 * BS_STRIDE)

// ---------------- scratch ----------------
__device__ float g_h[(size_t)N_NODES * FDIM];
__device__ float g_buf[(size_t)N_NODES * FDIM];
__device__ float g_asrc[N_NODES * HEADS];
__device__ float g_adst[N_NODES * HEADS];
__device__ int   g_counts[N_NODES];
__device__ int   g_off[N_NODES + 1];
__device__ int   g_cur[N_NODES];
__device__ int   g_csrc[ET];
__device__ int   g_bsum[64];
__device__ int   g_bbase[64];

__device__ __forceinline__ float lrelu(float x) { return x > 0.f ? x : NEG * x; }
__device__ __forceinline__ uint32_t f2tf32(float f) {
    uint32_t r;
    asm("cvt.rna.tf32.f32 %0, %1;" : "=r"(r) : "f"(f));
    return r;
}
__device__ __forceinline__ void mma16n8k8(float* d, const uint32_t* a, uint32_t b0, uint32_t b1) {
    asm volatile(
        "mma.sync.aligned.m16n8k8.row.col.f32.tf32.tf32.f32 "
        "{%0,%1,%2,%3}, {%4,%5,%6,%7}, {%8,%9}, {%0,%1,%2,%3};"
        : "+f"(d[0]), "+f"(d[1]), "+f"(d[2]), "+f"(d[3])
        : "r"(a[0]), "r"(a[1]), "r"(a[2]), "r"(a[3]), "r"(b0), "r"(b1));
}

// ---------------- zero counts ----------------
__global__ void k_zero_counts() {
    int i = blockIdx.x * blockDim.x + threadIdx.x;
    if (i < N_NODES) g_counts[i] = 0;
}

// ---------------- degree histogram (grid-strided) ----------------
__global__ void k_hist(const int* __restrict__ ei) {
    for (int i = blockIdx.x * blockDim.x + threadIdx.x; i < ET; i += gridDim.x * blockDim.x) {
        int d = (i < N_EDGES) ? ei[N_EDGES + i] : (i - N_EDGES);
        atomicAdd(&g_counts[d], 1);
    }
}

// ---------------- parallel 3-phase scan ----------------
__global__ void __launch_bounds__(1024) k_scan1() {
    __shared__ int sh[1024];
    int tid = threadIdx.x;
    int i = blockIdx.x * 1024 + tid;
    int v = (i < N_NODES) ? g_counts[i] : 0;
    sh[tid] = v;
    __syncthreads();
#pragma unroll
    for (int off = 1; off < 1024; off <<= 1) {
        int t = (tid >= off) ? sh[tid - off] : 0;
        __syncthreads();
        sh[tid] += t;
        __syncthreads();
    }
    if (i < N_NODES) g_off[i] = sh[tid] - v;   // local exclusive prefix
    if (tid == 1023) g_bsum[blockIdx.x] = sh[1023];
}

__global__ void k_scan2() {
    __shared__ int sh[64];
    int tid = threadIdx.x;   // 64 threads
    int v = (tid < SCAN_BLOCKS) ? g_bsum[tid] : 0;
    sh[tid] = v;
    __syncthreads();
#pragma unroll
    for (int off = 1; off < 64; off <<= 1) {
        int t = (tid >= off) ? sh[tid - off] : 0;
        __syncthreads();
        sh[tid] += t;
        __syncthreads();
    }
    if (tid < SCAN_BLOCKS) g_bbase[tid] = sh[tid] - v;   // exclusive
    if (tid == 63) g_off[N_NODES] = sh[63];
}

__global__ void k_scan3() {
    int i = blockIdx.x * blockDim.x + threadIdx.x;
    if (i < N_NODES) {
        int o = g_off[i] + g_bbase[i >> 10];
        g_off[i] = o;
        g_cur[i] = o;
    }
}

// ---------------- tensor-core tf32 GEMM: g_h[N,128] = X @ W[128,128] ----------------
__global__ void __launch_bounds__(256) k_gemm(const float* __restrict__ Xext,
                                              const float* __restrict__ W) {
    extern __shared__ uint32_t sm[];
    uint32_t* As = sm;                 // [128][68]
    uint32_t* Bs = sm + AS_WORDS;      // [64][136]
    const float* X = Xext ? Xext : (const float*)g_buf;
    const int tid = threadIdx.x;
    const int wid = tid >> 5, lane = tid & 31;
    const int g = lane >> 2, t = lane & 3;
    const int wm = wid & 3, wn = wid >> 2;
    const int row0 = blockIdx.x * 128;

    float d[2][8][4];
#pragma unroll
    for (int mi = 0; mi < 2; mi++)
#pragma unroll
        for (int ni = 0; ni < 8; ni++)
#pragma unroll
            for (int k = 0; k < 4; k++) d[mi][ni][k] = 0.f;

    for (int kc = 0; kc < 128; kc += 64) {
#pragma unroll
        for (int it = 0; it < 8; it++) {
            int idx = tid + it * 256;
            int r = idx >> 4, c4 = (idx & 15) * 4;
            int gr = row0 + r;
            uint32_t o0 = 0, o1 = 0, o2 = 0, o3 = 0;
            if (gr < N_NODES) {
                float4 v = *(const float4*)&X[(size_t)gr * FDIM + kc + c4];
                o0 = f2tf32(v.x); o1 = f2tf32(v.y); o2 = f2tf32(v.z); o3 = f2tf32(v.w);
            }
            uint32_t* p = &As[r * AS_STRIDE + c4];
            p[0] = o0; p[1] = o1; p[2] = o2; p[3] = o3;
        }
#pragma unroll
        for (int it = 0; it < 8; it++) {
            int idx = tid + it * 256;
            int k = idx >> 5, n4 = (idx & 31) * 4;
            float4 v = *(const float4*)&W[(size_t)(kc + k) * FDIM + n4];
            uint32_t* p = &Bs[k * BS_STRIDE + n4];
            p[0] = f2tf32(v.x); p[1] = f2tf32(v.y); p[2] = f2tf32(v.z); p[3] = f2tf32(v.w);
        }
        __syncthreads();

#pragma unroll
        for (int ks = 0; ks < 8; ks++) {
            const int k0 = ks * 8;
            uint32_t a[2][4];
#pragma unroll
            for (int mi = 0; mi < 2; mi++) {
                int rb = wm * 32 + mi * 16;
                a[mi][0] = As[(rb + g) * AS_STRIDE + k0 + t];
                a[mi][1] = As[(rb + g + 8) * AS_STRIDE + k0 + t];
                a[mi][2] = As[(rb + g) * AS_STRIDE + k0 + t + 4];
                a[mi][3] = As[(rb + g + 8) * AS_STRIDE + k0 + t + 4];
            }
#pragma unroll
            for (int ni = 0; ni < 8; ni++) {
                int nb = wn * 64 + ni * 8;
                uint32_t b0 = Bs[(k0 + t) * BS_STRIDE + nb + g];
                uint32_t b1 = Bs[(k0 + t + 4) * BS_STRIDE + nb + g];
                mma16n8k8(d[0][ni], a[0], b0, b1);
                mma16n8k8(d[1][ni], a[1], b0, b1);
            }
        }
        __syncthreads();
    }

#pragma unroll
    for (int mi = 0; mi < 2; mi++) {
        int r0 = row0 + wm * 32 + mi * 16 + g;
        int r1 = r0 + 8;
#pragma unroll
        for (int ni = 0; ni < 8; ni++) {
            int col = wn * 64 + ni * 8 + t * 2;
            if (r0 < N_NODES) *(float2*)&g_h[(size_t)r0 * FDIM + col] = make_float2(d[mi][ni][0], d[mi][ni][1]);
            if (r1 < N_NODES) *(float2*)&g_h[(size_t)r1 * FDIM + col] = make_float2(d[mi][ni][2], d[mi][ni][3]);
        }
    }
}

// ---------------- fused attdot (warp per node) + CSR scatter ----------------
__global__ void k_attdot_scatter(const float* __restrict__ att_s,
                                 const float* __restrict__ att_d,
                                 const int* __restrict__ ei) {
    if (blockIdx.x >= ATT_BLOCKS) {
        if (ei) {
            int i = (blockIdx.x - ATT_BLOCKS) * 256 + threadIdx.x;
            if (i < ET) {
                int s, d;
                if (i < N_EDGES) { s = ei[i]; d = ei[N_EDGES + i]; }
                else             { s = i - N_EDGES; d = s; }
                int pos = atomicAdd(&g_cur[d], 1);
                g_csrc[pos] = s;
            }
        }
        return;
    }
    int gw = (blockIdx.x * 256 + threadIdx.x) >> 5;
    int lane = threadIdx.x & 31;
    if (gw >= N_NODES) return;
    int head = lane >> 3, idx = lane & 7;
    int c = head * 32 + idx * 4;
    float4 hv = *(const float4*)&g_h[(size_t)gw * FDIM + c];
    float4 a1 = *(const float4*)&att_s[c];
    float4 a2 = *(const float4*)&att_d[c];
    float vs = hv.x * a1.x + hv.y * a1.y + hv.z * a1.z + hv.w * a1.w;
    float vd = hv.x * a2.x + hv.y * a2.y + hv.z * a2.z + hv.w * a2.w;
    vs += __shfl_down_sync(0xffffffffu, vs, 4);
    vs += __shfl_down_sync(0xffffffffu, vs, 2);
    vs += __shfl_down_sync(0xffffffffu, vs, 1);
    vd += __shfl_down_sync(0xffffffffu, vd, 4);
    vd += __shfl_down_sync(0xffffffffu, vd, 2);
    vd += __shfl_down_sync(0xffffffffu, vd, 1);
    if (idx == 0) {
        g_asrc[gw * HEADS + head] = vs;
        g_adst[gw * HEADS + head] = vd;
    }
}

// ---------------- segment softmax + weighted aggregation (warp per dst node) ----------------
__global__ void __launch_bounds__(256) k_aggregate(const float* __restrict__ bias) {
    int d = (blockIdx.x * 256 + threadIdx.x) >> 5;
    int lane = threadIdx.x & 31;
    if (d >= N_NODES) return;
    const int beg = g_off[d], end = g_off[d + 1];

    float4 adv = *(const float4*)&g_adst[d * HEADS];
    const float ad0 = adv.x, ad1 = adv.y, ad2 = adv.z, ad3 = adv.w;

    float ea0, ea1, ea2, ea3, eb0, eb1, eb2, eb3;
    float m0 = -1e30f, m1 = -1e30f, m2 = -1e30f, m3 = -1e30f;
    int B = 0;
    for (int j = beg + lane; j < end; j += 32) {
        int s = g_csrc[j];
        float4 as = *(const float4*)&g_asrc[s * HEADS];
        float v0 = lrelu(as.x + ad0), v1 = lrelu(as.y + ad1);
        float v2 = lrelu(as.z + ad2), v3 = lrelu(as.w + ad3);
        if (B == 0)      { ea0 = v0; ea1 = v1; ea2 = v2; ea3 = v3; }
        else if (B == 1) { eb0 = v0; eb1 = v1; eb2 = v2; eb3 = v3; }
        m0 = fmaxf(m0, v0); m1 = fmaxf(m1, v1);
        m2 = fmaxf(m2, v2); m3 = fmaxf(m3, v3);
        B++;
    }
#pragma unroll
    for (int o = 16; o; o >>= 1) {
        m0 = fmaxf(m0, __shfl_xor_sync(0xffffffffu, m0, o));
        m1 = fmaxf(m1, __shfl_xor_sync(0xffffffffu, m1, o));
        m2 = fmaxf(m2, __shfl_xor_sync(0xffffffffu, m2, o));
        m3 = fmaxf(m3, __shfl_xor_sync(0xffffffffu, m3, o));
    }
    float s0 = 0.f, s1 = 0.f, s2 = 0.f, s3 = 0.f;
    if (B >= 1) {
        s0 += __expf(ea0 - m0); s1 += __expf(ea1 - m1);
        s2 += __expf(ea2 - m2); s3 += __expf(ea3 - m3);
    }
    if (B >= 2) {
        s0 += __expf(eb0 - m0); s1 += __expf(eb1 - m1);
        s2 += __expf(eb2 - m2); s3 += __expf(eb3 - m3);
    }
    for (int j = beg + lane + 64; j < end; j += 32) {
        int s = g_csrc[j];
        float4 as = *(const float4*)&g_asrc[s * HEADS];
        s0 += __expf(lrelu(as.x + ad0) - m0);
        s1 += __expf(lrelu(as.y + ad1) - m1);
        s2 += __expf(lrelu(as.z + ad2) - m2);
        s3 += __expf(lrelu(as.w + ad3) - m3);
    }
#pragma unroll
    for (int o = 16; o; o >>= 1) {
        s0 += __shfl_xor_sync(0xffffffffu, s0, o);
        s1 += __shfl_xor_sync(0xffffffffu, s1, o);
        s2 += __shfl_xor_sync(0xffffffffu, s2, o);
        s3 += __shfl_xor_sync(0xffffffffu, s3, o);
    }

    const int myh = lane >> 3;
    const float mh  = (myh == 0) ? m0 : (myh == 1) ? m1 : (myh == 2) ? m2 : m3;
    const float sh  = (myh == 0) ? s0 : (myh == 1) ? s1 : (myh == 2) ? s2 : s3;
    const float adm = (myh == 0) ? ad0 : (myh == 1) ? ad1 : (myh == 2) ? ad2 : ad3;
    const float inv = 1.f / sh;
    const float* __restrict__ asr = (const float*)g_asrc;
    const float* __restrict__ H   = (const float*)g_h;
    const int ch = lane * 4;

    float4 acc0 = make_float4(0.f, 0.f, 0.f, 0.f);
    float4 acc1 = make_float4(0.f, 0.f, 0.f, 0.f);
    int j = beg;
    for (; j + 4 <= end; j += 4) {
        int sA = g_csrc[j], sB = g_csrc[j + 1], sC = g_csrc[j + 2], sD = g_csrc[j + 3];
        float aA = asr[sA * HEADS + myh], aB = asr[sB * HEADS + myh];
        float aC = asr[sC * HEADS + myh], aD = asr[sD * HEADS + myh];
        float4 hA = *(const float4*)&H[(size_t)sA * FDIM + ch];
        float4 hB = *(const float4*)&H[(size_t)sB * FDIM + ch];
        float4 hC = *(const float4*)&H[(size_t)sC * FDIM + ch];
        float4 hD = *(const float4*)&H[(size_t)sD * FDIM + ch];
        float alA = __expf(lrelu(aA + adm) - mh) * inv;
        float alB = __expf(lrelu(aB + adm) - mh) * inv;
        float alC = __expf(lrelu(aC + adm) - mh) * inv;
        float alD = __expf(lrelu(aD + adm) - mh) * inv;
        acc0.x = fmaf(alA, hA.x, acc0.x); acc0.y = fmaf(alA, hA.y, acc0.y);
        acc0.z = fmaf(alA, hA.z, acc0.z); acc0.w = fmaf(alA, hA.w, acc0.w);
        acc1.x = fmaf(alB, hB.x, acc1.x); acc1.y = fmaf(alB, hB.y, acc1.y);
        acc1.z = fmaf(alB, hB.z, acc1.z); acc1.w = fmaf(alB, hB.w, acc1.w);
        acc0.x = fmaf(alC, hC.x, acc0.x); acc0.y = fmaf(alC, hC.y, acc0.y);
        acc0.z = fmaf(alC, hC.z, acc0.z); acc0.w = fmaf(alC, hC.w, acc0.w);
        acc1.x = fmaf(alD, hD.x, acc1.x); acc1.y = fmaf(alD, hD.y, acc1.y);
        acc1.z = fmaf(alD, hD.z, acc1.z); acc1.w = fmaf(alD, hD.w, acc1.w);
    }
    for (; j < end; j++) {
        int s = g_csrc[j];
        float a = asr[s * HEADS + myh];
        float4 hv = *(const float4*)&H[(size_t)s * FDIM + ch];
        float al = __expf(lrelu(a + adm) - mh) * inv;
        acc0.x = fmaf(al, hv.x, acc0.x); acc0.y = fmaf(al, hv.y, acc0.y);
        acc0.z = fmaf(al, hv.z, acc0.z); acc0.w = fmaf(al, hv.w, acc0.w);
    }
    float4 b = *(const float4*)&bias[ch];
    float4 r;
    r.x = fmaxf(acc0.x + acc1.x + b.x, 0.f);
    r.y = fmaxf(acc0.y + acc1.y + b.y, 0.f);
    r.z = fmaxf(acc0.z + acc1.z + b.z, 0.f);
    r.w = fmaxf(acc0.w + acc1.w + b.w, 0.f);
    *(float4*)&g_buf[(size_t)d * FDIM + ch] = r;
}

// ---------------- global mean pool + linear head ----------------
__global__ void k_pool(const int* __restrict__ batch,
                       const float* __restrict__ w_lin,
                       const float* __restrict__ b_lin,
                       float* __restrict__ out) {
    int g = blockIdx.x;
    __shared__ int s_lo, s_hi;
    __shared__ float pooled[FDIM];
    if (threadIdx.x == 0) {
        int lo = 0, hi = N_NODES;
        while (lo < hi) { int mid = (lo + hi) >> 1; if (batch[mid] < g) lo = mid + 1; else hi = mid; }
        s_lo = lo;
        hi = N_NODES;
        while (lo < hi) { int mid = (lo + hi) >> 1; if (batch[mid] < g + 1) lo = mid + 1; else hi = mid; }
        s_hi = lo;
    }
    __syncthreads();
    int lo = s_lo, hi = s_hi;
    float a0 = 0.f, a1 = 0.f, a2 = 0.f, a3 = 0.f;
    int n = lo;
    for (; n + 4 <= hi; n += 4) {
        a0 += g_buf[(size_t)(n + 0) * FDIM + threadIdx.x];
        a1 += g_buf[(size_t)(n + 1) * FDIM + threadIdx.x];
        a2 += g_buf[(size_t)(n + 2) * FDIM + threadIdx.x];
        a3 += g_buf[(size_t)(n + 3) * FDIM + threadIdx.x];
    }
    for (; n < hi; n++) a0 += g_buf[(size_t)n * FDIM + threadIdx.x];
    float cnt = (float)(hi - lo);
    pooled[threadIdx.x] = (a0 + a1 + a2 + a3) / fmaxf(cnt, 1.f);
    __syncthreads();
    if (threadIdx.x < OUT_CH) {
        float acc = b_lin[threadIdx.x];
        for (int c = 0; c < FDIM; c++) acc += pooled[c] * w_lin[c * OUT_CH + threadIdx.x];
        out[g * OUT_CH + threadIdx.x] = acc;
    }
}

// ---------------- launch ----------------
extern "C" void kernel_launch(void* const* d_in, const int* in_sizes, int n_in,
                              void* d_out, int out_size) {
    const float* x      = (const float*)d_in[0];
    const int*   ei     = (const int*)d_in[1];
    const int*   batch  = (const int*)d_in[2];
    const float* W1     = (const float*)d_in[3];
    const float* att_s1 = (const float*)d_in[4];
    const float* att_d1 = (const float*)d_in[5];
    const float* b1     = (const float*)d_in[6];
    const float* W2     = (const float*)d_in[7];
    const float* att_s2 = (const float*)d_in[8];
    const float* att_d2 = (const float*)d_in[9];
    const float* b2     = (const float*)d_in[10];
    const float* w_lin  = (const float*)d_in[11];
    const float* b_lin  = (const float*)d_in[12];
    float* out = (float*)d_out;

    const int SMEM_BYTES = SMEM_WORDS * 4;   // ~70KB
    cudaFuncSetAttribute(k_gemm, cudaFuncAttributeMaxDynamicSharedMemorySize, SMEM_BYTES);

    const int NB = (N_NODES + 255) / 256;
    const int WB = (N_NODES * 32 + 255) / 256;

    k_zero_counts<<<NB, 256>>>();
    k_hist<<<296, 256>>>(ei);

    // layer 1
    k_gemm<<<GEMM_BLOCKS, 256, SMEM_BYTES>>>(x, W1);
    k_scan1<<<SCAN_BLOCKS, 1024>>>();
    k_scan2<<<1, 64>>>();
    k_scan3<<<NB, 256>>>();
    k_attdot_scatter<<<ATT_BLOCKS + SCAT_BLOCKS, 256>>>(att_s1, att_d1, ei);
    k_aggregate<<<WB, 256>>>(b1);

    // layer 2
    k_gemm<<<GEMM_BLOCKS, 256, SMEM_BYTES>>>(nullptr, W2);
    k_attdot_scatter<<<ATT_BLOCKS, 256>>>(att_s2, att_d2, nullptr);
    k_aggregate<<<WB, 256>>>(b2);

    k_pool<<<N_GRAPHS, 128>>>(batch, w_lin, b_lin, out);
}

// round 8
// speedup vs baseline: 1.7563x; 1.0180x over previous
#include <cuda_runtime.h>
#include <cstdint>

#define N_NODES 50000
#define N_EDGES 800000
#define ET (N_EDGES + N_NODES)
#define FDIM 128
#define HEADS 4
#define N_GRAPHS 64
#define OUT_CH 10
#define NEG 0.2f

#define GEMM_BLOCKS ((N_NODES + 127) / 128)        // 391
#define SCAN_BLOCKS ((N_NODES + 1023) / 1024)      // 49

// SMEM for mma GEMM: As[128][68] + Bs[64][136] (tf32 bits) + att vectors (256 floats)
#define AS_STRIDE 68
#define BS_STRIDE 136
#define AS_WORDS (128 * AS_STRIDE)
#define SMEM_WORDS (AS_WORDS + 64 * BS_STRIDE)
#define SMEM_BYTES ((SMEM_WORDS + 256) * 4)

// ---------------- scratch ----------------
__device__ float g_h[(size_t)N_NODES * FDIM];
__device__ float g_buf[(size_t)N_NODES * FDIM];
__device__ float g_asrc[N_NODES * HEADS];
__device__ float g_adst[N_NODES * HEADS];
__device__ int   g_counts[N_NODES];
__device__ int   g_off[N_NODES + 1];
__device__ int   g_cur[N_NODES];
__device__ int   g_csrc[ET];
__device__ int   g_bsum[64];
__device__ int   g_bbase[64];

__device__ __forceinline__ float lrelu(float x) { return x > 0.f ? x : NEG * x; }
__device__ __forceinline__ uint32_t f2tf32(float f) {
    uint32_t r;
    asm("cvt.rna.tf32.f32 %0, %1;" : "=r"(r) : "f"(f));
    return r;
}
__device__ __forceinline__ void mma16n8k8(float* d, const uint32_t* a, uint32_t b0, uint32_t b1) {
    asm volatile(
        "mma.sync.aligned.m16n8k8.row.col.f32.tf32.tf32.f32 "
        "{%0,%1,%2,%3}, {%4,%5,%6,%7}, {%8,%9}, {%0,%1,%2,%3};"
        : "+f"(d[0]), "+f"(d[1]), "+f"(d[2]), "+f"(d[3])
        : "r"(a[0]), "r"(a[1]), "r"(a[2]), "r"(a[3]), "r"(b0), "r"(b1));
}

// ---------------- init counts to 1 (self loops pre-counted) ----------------
__global__ void k_init_counts() {
    int i = blockIdx.x * blockDim.x + threadIdx.x;
    if (i < N_NODES) g_counts[i] = 1;
}

// ---------------- degree histogram: vectorized over dst half of edge_index ----------------
__global__ void k_hist(const int* __restrict__ ei) {
    const int4* dst4 = (const int4*)(ei + N_EDGES);
    for (int i = blockIdx.x * blockDim.x + threadIdx.x; i < N_EDGES / 4; i += gridDim.x * blockDim.x) {
        int4 d = dst4[i];
        atomicAdd(&g_counts[d.x], 1);
        atomicAdd(&g_counts[d.y], 1);
        atomicAdd(&g_counts[d.z], 1);
        atomicAdd(&g_counts[d.w], 1);
    }
}

// ---------------- parallel 3-phase scan ----------------
__global__ void __launch_bounds__(1024) k_scan1() {
    __shared__ int sh[1024];
    int tid = threadIdx.x;
    int i = blockIdx.x * 1024 + tid;
    int v = (i < N_NODES) ? g_counts[i] : 0;
    sh[tid] = v;
    __syncthreads();
#pragma unroll
    for (int off = 1; off < 1024; off <<= 1) {
        int t = (tid >= off) ? sh[tid - off] : 0;
        __syncthreads();
        sh[tid] += t;
        __syncthreads();
    }
    if (i < N_NODES) g_off[i] = sh[tid] - v;
    if (tid == 1023) g_bsum[blockIdx.x] = sh[1023];
}

__global__ void k_scan2() {
    __shared__ int sh[64];
    int tid = threadIdx.x;
    int v = (tid < SCAN_BLOCKS) ? g_bsum[tid] : 0;
    sh[tid] = v;
    __syncthreads();
#pragma unroll
    for (int off = 1; off < 64; off <<= 1) {
        int t = (tid >= off) ? sh[tid - off] : 0;
        __syncthreads();
        sh[tid] += t;
        __syncthreads();
    }
    if (tid < SCAN_BLOCKS) g_bbase[tid] = sh[tid] - v;
    if (tid == 63) g_off[N_NODES] = sh[63];
}

__global__ void k_scan3() {
    int i = blockIdx.x * blockDim.x + threadIdx.x;
    if (i < N_NODES) {
        int o = g_off[i] + g_bbase[i >> 10];
        g_off[i] = o;
        g_cur[i] = o;
    }
}

// ---------------- CSR scatter (grid-strided) ----------------
__global__ void k_scatter(const int* __restrict__ ei) {
    for (int i = blockIdx.x * blockDim.x + threadIdx.x; i < ET; i += gridDim.x * blockDim.x) {
        int s, d;
        if (i < N_EDGES) { s = ei[i]; d = ei[N_EDGES + i]; }
        else             { s = i - N_EDGES; d = s; }
        int pos = atomicAdd(&g_cur[d], 1);
        g_csrc[pos] = s;
    }
}

// ---------------- tensor-core tf32 GEMM + fused attention dots ----------------
// g_h[N,128] = X @ W; g_asrc/g_adst computed from in-register accumulators.
__global__ void __launch_bounds__(256) k_gemm(const float* __restrict__ Xext,
                                              const float* __restrict__ W,
                                              const float* __restrict__ att_s,
                                              const float* __restrict__ att_d) {
    extern __shared__ uint32_t sm[];
    uint32_t* As = sm;                 // [128][68]
    uint32_t* Bs = sm + AS_WORDS;      // [64][136]
    float* as_sm = (float*)(sm + SMEM_WORDS);
    float* ad_sm = as_sm + 128;
    const float* X = Xext ? Xext : (const float*)g_buf;
    const int tid = threadIdx.x;
    const int wid = tid >> 5, lane = tid & 31;
    const int g = lane >> 2, t = lane & 3;
    const int wm = wid & 3, wn = wid >> 2;
    const int row0 = blockIdx.x * 128;

    if (tid < 128)      as_sm[tid] = att_s[tid];
    else                ad_sm[tid - 128] = att_d[tid - 128];

    float d[2][8][4];
#pragma unroll
    for (int mi = 0; mi < 2; mi++)
#pragma unroll
        for (int ni = 0; ni < 8; ni++)
#pragma unroll
            for (int k = 0; k < 4; k++) d[mi][ni][k] = 0.f;

    for (int kc = 0; kc < 128; kc += 64) {
#pragma unroll
        for (int it = 0; it < 8; it++) {
            int idx = tid + it * 256;
            int r = idx >> 4, c4 = (idx & 15) * 4;
            int gr = row0 + r;
            uint32_t o0 = 0, o1 = 0, o2 = 0, o3 = 0;
            if (gr < N_NODES) {
                float4 v = *(const float4*)&X[(size_t)gr * FDIM + kc + c4];
                o0 = f2tf32(v.x); o1 = f2tf32(v.y); o2 = f2tf32(v.z); o3 = f2tf32(v.w);
            }
            uint32_t* p = &As[r * AS_STRIDE + c4];
            p[0] = o0; p[1] = o1; p[2] = o2; p[3] = o3;
        }
#pragma unroll
        for (int it = 0; it < 8; it++) {
            int idx = tid + it * 256;
            int k = idx >> 5, n4 = (idx & 31) * 4;
            float4 v = *(const float4*)&W[(size_t)(kc + k) * FDIM + n4];
            uint32_t* p = &Bs[k * BS_STRIDE + n4];
            p[0] = f2tf32(v.x); p[1] = f2tf32(v.y); p[2] = f2tf32(v.z); p[3] = f2tf32(v.w);
        }
        __syncthreads();

#pragma unroll
        for (int ks = 0; ks < 8; ks++) {
            const int k0 = ks * 8;
            uint32_t a[2][4];
#pragma unroll
            for (int mi = 0; mi < 2; mi++) {
                int rb = wm * 32 + mi * 16;
                a[mi][0] = As[(rb + g) * AS_STRIDE + k0 + t];
                a[mi][1] = As[(rb + g + 8) * AS_STRIDE + k0 + t];
                a[mi][2] = As[(rb + g) * AS_STRIDE + k0 + t + 4];
                a[mi][3] = As[(rb + g + 8) * AS_STRIDE + k0 + t + 4];
            }
#pragma unroll
            for (int ni = 0; ni < 8; ni++) {
                int nb = wn * 64 + ni * 8;
                uint32_t b0 = Bs[(k0 + t) * BS_STRIDE + nb + g];
                uint32_t b1 = Bs[(k0 + t + 4) * BS_STRIDE + nb + g];
                mma16n8k8(d[0][ni], a[0], b0, b1);
                mma16n8k8(d[1][ni], a[1], b0, b1);
            }
        }
        __syncthreads();
    }

    // epilogue: store h + fused per-head attention dots.
    // head h0 = 2*wn covers ni 0..3; head h1 = 2*wn+1 covers ni 4..7 (32 cols each, complete in-warp).
    const int h0 = 2 * wn;
#pragma unroll
    for (int mi = 0; mi < 2; mi++) {
        int r0 = row0 + wm * 32 + mi * 16 + g;
        int r1 = r0 + 8;
        float s0a = 0.f, s0b = 0.f, d0a = 0.f, d0b = 0.f;   // row r0, heads h0/h0+1
        float s1a = 0.f, s1b = 0.f, d1a = 0.f, d1b = 0.f;   // row r1
#pragma unroll
        for (int ni = 0; ni < 8; ni++) {
            int col = wn * 64 + ni * 8 + t * 2;
            float w0s = as_sm[col], w1s = as_sm[col + 1];
            float w0d = ad_sm[col], w1d = ad_sm[col + 1];
            float v00 = d[mi][ni][0], v01 = d[mi][ni][1];
            float v10 = d[mi][ni][2], v11 = d[mi][ni][3];
            if (r0 < N_NODES) *(float2*)&g_h[(size_t)r0 * FDIM + col] = make_float2(v00, v01);
            if (r1 < N_NODES) *(float2*)&g_h[(size_t)r1 * FDIM + col] = make_float2(v10, v11);
            if (ni < 4) {
                s0a = fmaf(v00, w0s, fmaf(v01, w1s, s0a));
                d0a = fmaf(v00, w0d, fmaf(v01, w1d, d0a));
                s1a = fmaf(v10, w0s, fmaf(v11, w1s, s1a));
                d1a = fmaf(v10, w0d, fmaf(v11, w1d, d1a));
            } else {
                s0b = fmaf(v00, w0s, fmaf(v01, w1s, s0b));
                d0b = fmaf(v00, w0d, fmaf(v01, w1d, d0b));
                s1b = fmaf(v10, w0s, fmaf(v11, w1s, s1b));
                d1b = fmaf(v10, w0d, fmaf(v11, w1d, d1b));
            }
        }
        // reduce over t (lanes g*4 + t)
#pragma unroll
        for (int o = 1; o <= 2; o <<= 1) {
            s0a += __shfl_down_sync(0xffffffffu, s0a, o);
            s0b += __shfl_down_sync(0xffffffffu, s0b, o);
            d0a += __shfl_down_sync(0xffffffffu, d0a, o);
            d0b += __shfl_down_sync(0xffffffffu, d0b, o);
            s1a += __shfl_down_sync(0xffffffffu, s1a, o);
            s1b += __shfl_down_sync(0xffffffffu, s1b, o);
            d1a += __shfl_down_sync(0xffffffffu, d1a, o);
            d1b += __shfl_down_sync(0xffffffffu, d1b, o);
        }
        if (t == 0) {
            if (r0 < N_NODES) {
                g_asrc[r0 * HEADS + h0] = s0a; g_asrc[r0 * HEADS + h0 + 1] = s0b;
                g_adst[r0 * HEADS + h0] = d0a; g_adst[r0 * HEADS + h0 + 1] = d0b;
            }
            if (r1 < N_NODES) {
                g_asrc[r1 * HEADS + h0] = s1a; g_asrc[r1 * HEADS + h0 + 1] = s1b;
                g_adst[r1 * HEADS + h0] = d1a; g_adst[r1 * HEADS + h0 + 1] = d1b;
            }
        }
    }
}

// ---------------- segment softmax + weighted aggregation (warp per dst node) ----------------
__global__ void __launch_bounds__(256) k_aggregate(const float* __restrict__ bias) {
    int d = (blockIdx.x * 256 + threadIdx.x) >> 5;
    int lane = threadIdx.x & 31;
    if (d >= N_NODES) return;
    const int beg = g_off[d], end = g_off[d + 1];

    float4 adv = *(const float4*)&g_adst[d * HEADS];
    const float ad0 = adv.x, ad1 = adv.y, ad2 = adv.z, ad3 = adv.w;

    float ea0, ea1, ea2, ea3, eb0, eb1, eb2, eb3;
    float m0 = -1e30f, m1 = -1e30f, m2 = -1e30f, m3 = -1e30f;
    int B = 0;
    for (int j = beg + lane; j < end; j += 32) {
        int s = g_csrc[j];
        float4 as = *(const float4*)&g_asrc[s * HEADS];
        float v0 = lrelu(as.x + ad0), v1 = lrelu(as.y + ad1);
        float v2 = lrelu(as.z + ad2), v3 = lrelu(as.w + ad3);
        if (B == 0)      { ea0 = v0; ea1 = v1; ea2 = v2; ea3 = v3; }
        else if (B == 1) { eb0 = v0; eb1 = v1; eb2 = v2; eb3 = v3; }
        m0 = fmaxf(m0, v0); m1 = fmaxf(m1, v1);
        m2 = fmaxf(m2, v2); m3 = fmaxf(m3, v3);
        B++;
    }
#pragma unroll
    for (int o = 16; o; o >>= 1) {
        m0 = fmaxf(m0, __shfl_xor_sync(0xffffffffu, m0, o));
        m1 = fmaxf(m1, __shfl_xor_sync(0xffffffffu, m1, o));
        m2 = fmaxf(m2, __shfl_xor_sync(0xffffffffu, m2, o));
        m3 = fmaxf(m3, __shfl_xor_sync(0xffffffffu, m3, o));
    }
    float s0 = 0.f, s1 = 0.f, s2 = 0.f, s3 = 0.f;
    if (B >= 1) {
        s0 += __expf(ea0 - m0); s1 += __expf(ea1 - m1);
        s2 += __expf(ea2 - m2); s3 += __expf(ea3 - m3);
    }
    if (B >= 2) {
        s0 += __expf(eb0 - m0); s1 += __expf(eb1 - m1);
        s2 += __expf(eb2 - m2); s3 += __expf(eb3 - m3);
    }
    for (int j = beg + lane + 64; j < end; j += 32) {
        int s = g_csrc[j];
        float4 as = *(const float4*)&g_asrc[s * HEADS];
        s0 += __expf(lrelu(as.x + ad0) - m0);
        s1 += __expf(lrelu(as.y + ad1) - m1);
        s2 += __expf(lrelu(as.z + ad2) - m2);
        s3 += __expf(lrelu(as.w + ad3) - m3);
    }
#pragma unroll
    for (int o = 16; o; o >>= 1) {
        s0 += __shfl_xor_sync(0xffffffffu, s0, o);
        s1 += __shfl_xor_sync(0xffffffffu, s1, o);
        s2 += __shfl_xor_sync(0xffffffffu, s2, o);
        s3 += __shfl_xor_sync(0xffffffffu, s3, o);
    }

    const int myh = lane >> 3;
    const float mh  = (myh == 0) ? m0 : (myh == 1) ? m1 : (myh == 2) ? m2 : m3;
    const float sh  = (myh == 0) ? s0 : (myh == 1) ? s1 : (myh == 2) ? s2 : s3;
    const float adm = (myh == 0) ? ad0 : (myh == 1) ? ad1 : (myh == 2) ? ad2 : ad3;
    const float inv = 1.f / sh;
    const float* __restrict__ asr = (const float*)g_asrc;
    const float* __restrict__ H   = (const float*)g_h;
    const int ch = lane * 4;

    float4 acc0 = make_float4(0.f, 0.f, 0.f, 0.f);
    float4 acc1 = make_float4(0.f, 0.f, 0.f, 0.f);
    int j = beg;
    for (; j + 8 <= end; j += 8) {
        int sI[8];
#pragma unroll
        for (int u = 0; u < 8; u++) sI[u] = g_csrc[j + u];
        float aI[8];
#pragma unroll
        for (int u = 0; u < 8; u++) aI[u] = asr[sI[u] * HEADS + myh];
        float4 hI[8];
#pragma unroll
        for (int u = 0; u < 8; u++) hI[u] = *(const float4*)&H[(size_t)sI[u] * FDIM + ch];
        float al[8];
#pragma unroll
        for (int u = 0; u < 8; u++) al[u] = __expf(lrelu(aI[u] + adm) - mh) * inv;
#pragma unroll
        for (int u = 0; u < 8; u += 2) {
            acc0.x = fmaf(al[u], hI[u].x, acc0.x);     acc0.y = fmaf(al[u], hI[u].y, acc0.y);
            acc0.z = fmaf(al[u], hI[u].z, acc0.z);     acc0.w = fmaf(al[u], hI[u].w, acc0.w);
            acc1.x = fmaf(al[u+1], hI[u+1].x, acc1.x); acc1.y = fmaf(al[u+1], hI[u+1].y, acc1.y);
            acc1.z = fmaf(al[u+1], hI[u+1].z, acc1.z); acc1.w = fmaf(al[u+1], hI[u+1].w, acc1.w);
        }
    }
    for (; j < end; j++) {
        int s = g_csrc[j];
        float a = asr[s * HEADS + myh];
        float4 hv = *(const float4*)&H[(size_t)s * FDIM + ch];
        float al = __expf(lrelu(a + adm) - mh) * inv;
        acc0.x = fmaf(al, hv.x, acc0.x); acc0.y = fmaf(al, hv.y, acc0.y);
        acc0.z = fmaf(al, hv.z, acc0.z); acc0.w = fmaf(al, hv.w, acc0.w);
    }
    float4 b = *(const float4*)&bias[ch];
    float4 r;
    r.x = fmaxf(acc0.x + acc1.x + b.x, 0.f);
    r.y = fmaxf(acc0.y + acc1.y + b.y, 0.f);
    r.z = fmaxf(acc0.z + acc1.z + b.z, 0.f);
    r.w = fmaxf(acc0.w + acc1.w + b.w, 0.f);
    *(float4*)&g_buf[(size_t)d * FDIM + ch] = r;
}

// ---------------- global mean pool + linear head ----------------
__global__ void k_pool(const int* __restrict__ batch,
                       const float* __restrict__ w_lin,
                       const float* __restrict__ b_lin,
                       float* __restrict__ out) {
    int g = blockIdx.x;
    __shared__ int s_lo, s_hi;
    __shared__ float pooled[FDIM];
    if (threadIdx.x == 0) {
        int lo = 0, hi = N_NODES;
        while (lo < hi) { int mid = (lo + hi) >> 1; if (batch[mid] < g) lo = mid + 1; else hi = mid; }
        s_lo = lo;
        hi = N_NODES;
        while (lo < hi) { int mid = (lo + hi) >> 1; if (batch[mid] < g + 1) lo = mid + 1; else hi = mid; }
        s_hi = lo;
    }
    __syncthreads();
    int lo = s_lo, hi = s_hi;
    float a0 = 0.f, a1 = 0.f, a2 = 0.f, a3 = 0.f;
    int n = lo;
    for (; n + 4 <= hi; n += 4) {
        a0 += g_buf[(size_t)(n + 0) * FDIM + threadIdx.x];
        a1 += g_buf[(size_t)(n + 1) * FDIM + threadIdx.x];
        a2 += g_buf[(size_t)(n + 2) * FDIM + threadIdx.x];
        a3 += g_buf[(size_t)(n + 3) * FDIM + threadIdx.x];
    }
    for (; n < hi; n++) a0 += g_buf[(size_t)n * FDIM + threadIdx.x];
    float cnt = (float)(hi - lo);
    pooled[threadIdx.x] = (a0 + a1 + a2 + a3) / fmaxf(cnt, 1.f);
    __syncthreads();
    if (threadIdx.x < OUT_CH) {
        float acc = b_lin[threadIdx.x];
        for (int c = 0; c < FDIM; c++) acc += pooled[c] * w_lin[c * OUT_CH + threadIdx.x];
        out[g * OUT_CH + threadIdx.x] = acc;
    }
}

// ---------------- launch ----------------
extern "C" void kernel_launch(void* const* d_in, const int* in_sizes, int n_in,
                              void* d_out, int out_size) {
    const float* x      = (const float*)d_in[0];
    const int*   ei     = (const int*)d_in[1];
    const int*   batch  = (const int*)d_in[2];
    const float* W1     = (const float*)d_in[3];
    const float* att_s1 = (const float*)d_in[4];
    const float* att_d1 = (const float*)d_in[5];
    const float* b1     = (const float*)d_in[6];
    const float* W2     = (const float*)d_in[7];
    const float* att_s2 = (const float*)d_in[8];
    const float* att_d2 = (const float*)d_in[9];
    const float* b2     = (const float*)d_in[10];
    const float* w_lin  = (const float*)d_in[11];
    const float* b_lin  = (const float*)d_in[12];
    float* out = (float*)d_out;

    cudaFuncSetAttribute(k_gemm, cudaFuncAttributeMaxDynamicSharedMemorySize, SMEM_BYTES);

    const int NB = (N_NODES + 255) / 256;
    const int WB = (N_NODES * 32 + 255) / 256;

    k_init_counts<<<NB, 256>>>();          // 1
    k_hist<<<200, 256>>>(ei);              // 2
    k_scan1<<<SCAN_BLOCKS, 1024>>>();      // 3
    k_scan2<<<1, 64>>>();                  // 4
    k_scan3<<<NB, 256>>>();                // 5

    // layer 1 (6th launch -> ncu profiles the fused GEMM)
    k_gemm<<<GEMM_BLOCKS, 256, SMEM_BYTES>>>(x, W1, att_s1, att_d1);   // 6
    k_scatter<<<888, 256>>>(ei);                                       // 7
    k_aggregate<<<WB, 256>>>(b1);                                      // 8

    // layer 2
    k_gemm<<<GEMM_BLOCKS, 256, SMEM_BYTES>>>(nullptr, W2, att_s2, att_d2);
    k_aggregate<<<WB, 256>>>(b2);

    k_pool<<<N_GRAPHS, 128>>>(batch, w_lin, b_lin, out);
}